// round 9
// baseline (speedup 1.0000x reference)
#include <cuda_runtime.h>
#include <cuda_bf16.h>
#include <math.h>
#include <stdint.h>

// Problem constants
#define Bz   4
#define Sz   1024
#define Dz   1024
#define Hz   16
#define SEz  77
#define DEz  768
#define DFFz 4096
#define M1   (Bz * Sz)          // 4096
#define MEnc (Bz * SEz)         // 308
#define NACT ((size_t)M1 * Dz)  // 4,194,304

// ---------------- scratch (static __device__, allocation-free) ----------------
__device__ float g_q1[NACT], g_q2[NACT];
__device__ float g_ffp[(size_t)M1 * 2 * DFFz];   // also hosts fused qkv / enc-kv staging
__device__ float g_qkv2[(size_t)M1 * 4 * Dz];    // FIXED: full M1 x 4096

// bf16 hi/lo operand buffers
__device__ __nv_bfloat16 sA1h[NACT], sA1l[NACT], sA2h[NACT], sA2l[NACT];
__device__ __nv_bfloat16 sT1h[NACT], sT1l[NACT], sT2h[NACT], sT2l[NACT];
__device__ __nv_bfloat16 sEh[(size_t)MEnc * DEz], sEl[(size_t)MEnc * DEz];
__device__ __nv_bfloat16 sFh[(size_t)M1 * DFFz], sFl[(size_t)M1 * DFFz];
__device__ __nv_bfloat16 sWh[(size_t)Dz * 2 * DFFz], sWl[(size_t)Dz * 2 * DFFz];

// ====================== common helpers ======================
__device__ __forceinline__ uint32_t smem_u32(const void* p) {
    uint32_t a;
    asm("{ .reg .u64 t; cvta.to.shared.u64 t, %1; cvt.u32.u64 %0, t; }" : "=r"(a) : "l"(p));
    return a;
}
__device__ __forceinline__ void mma16816(float* c, const uint32_t* a, const uint32_t* b) {
    asm volatile(
        "mma.sync.aligned.m16n8k16.row.col.f32.bf16.bf16.f32 "
        "{%0,%1,%2,%3}, {%4,%5,%6,%7}, {%8,%9}, {%0,%1,%2,%3};"
        : "+f"(c[0]), "+f"(c[1]), "+f"(c[2]), "+f"(c[3])
        : "r"(a[0]), "r"(a[1]), "r"(a[2]), "r"(a[3]), "r"(b[0]), "r"(b[1]));
}
__device__ __forceinline__ void ldsm4(uint32_t* r, uint32_t addr) {
    asm volatile("ldmatrix.sync.aligned.m8n8.x4.shared.b16 {%0,%1,%2,%3}, [%4];"
        : "=r"(r[0]), "=r"(r[1]), "=r"(r[2]), "=r"(r[3]) : "r"(addr));
}
__device__ __forceinline__ void ldsm4t(uint32_t* r, uint32_t addr) {
    asm volatile("ldmatrix.sync.aligned.m8n8.x4.trans.shared.b16 {%0,%1,%2,%3}, [%4];"
        : "=r"(r[0]), "=r"(r[1]), "=r"(r[2]), "=r"(r[3]) : "r"(addr));
}
__device__ __forceinline__ void cpa16(uint32_t saddr, const void* g, int src_sz) {
    asm volatile("cp.async.ca.shared.global [%0], [%1], 16, %2;"
        :: "r"(saddr), "l"(g), "r"(src_sz));
}
#define CPA_COMMIT() asm volatile("cp.async.commit_group;" ::: "memory")
#define CPA_WAIT0()  asm volatile("cp.async.wait_group 0;" ::: "memory")
#define CPA_WAIT1()  asm volatile("cp.async.wait_group 1;" ::: "memory")

__device__ __forceinline__ uint32_t pack_hi(float x, float y) {
    __nv_bfloat162 h(__float2bfloat16(x), __float2bfloat16(y));
    return *(uint32_t*)&h;
}
__device__ __forceinline__ uint32_t pack_lo(float x, float y) {
    float hx = __bfloat162float(__float2bfloat16(x));
    float hy = __bfloat162float(__float2bfloat16(y));
    __nv_bfloat162 l(__float2bfloat16(x - hx), __float2bfloat16(y - hy));
    return *(uint32_t*)&l;
}
// fast exp on FMA pipe (rel err ~2e-6)
__device__ __forceinline__ float fexp(float x) {
    float y = x * 1.4426950408889634f;
    float n = rintf(y);
    float f = y - n;
    float p = 1.5403530e-4f;
    p = fmaf(p, f, 0.0013333558f);
    p = fmaf(p, f, 0.0096181291f);
    p = fmaf(p, f, 0.0555041087f);
    p = fmaf(p, f, 0.2402265070f);
    p = fmaf(p, f, 0.6931471806f);
    p = fmaf(p, f, 1.0f);
    int e = (int)n;
    float r = __int_as_float((e + 127) << 23) * p;
    return (x < -80.f) ? 0.f : r;
}

// ====================== bf16 hi/lo GEMM: BM=64, BN=128, BK=32, 128 thr, 4 CTA/SM ======
#define G_ALO   5120
#define G_BOFF  10240
#define G_BHALF 8704
#define G_STAGE 27648
#define G_SMEM  (2 * G_STAGE)   // 55296

__global__ __launch_bounds__(128, 4)
void gemm_bf(const __nv_bfloat16* __restrict__ Agh, const __nv_bfloat16* __restrict__ Agl,
             const __nv_bfloat16* __restrict__ Bgh, const __nv_bfloat16* __restrict__ Bgl,
             const float* __restrict__ bias, const float* __restrict__ resid,
             float* __restrict__ C, int M, int N, int K)
{
    extern __shared__ char smraw[];
    const uint32_t sbase = smem_u32(smraw);
    const int tid = threadIdx.x, wid = tid >> 5, lane = tid & 31;
    const int g = lane >> 2, t4 = lane & 3;
    const int warp_m = wid >> 1, warp_n = wid & 1;     // 2 x 2 warps
    const int bm = blockIdx.y * 64, bn = blockIdx.x * 128;

    // ldmatrix address lanes
    const int r8 = lane & 7, q = lane >> 3;
    const int a_row  = r8 + (q & 1) * 8;
    const int a_koff = (q >> 1) * 16;          // bytes
    const int b_k    = r8 + (q >> 1) * 8;
    const int b_noff = (q & 1) * 8;            // elems

    // loader lanes: A 64 rows x 4 chunks; B 32 rows x 16 chunks
    const int am = tid >> 1, ac = (tid & 1) * 2;
    const int bk = tid >> 2, bc = (tid & 3) * 4;
    const bool aok = (bm + am) < M;
    const int asz = aok ? 16 : 0;

    float acc[2][8][4];
    #pragma unroll
    for (int mi = 0; mi < 2; ++mi)
        #pragma unroll
        for (int ni = 0; ni < 8; ++ni)
            #pragma unroll
            for (int j = 0; j < 4; ++j) acc[mi][ni][j] = 0.f;

    const int KT = K / 32;

    auto load_stage = [&](int s, int k0) {
        uint32_t sb = sbase + (uint32_t)s * G_STAGE;
        size_t aoff = (size_t)(bm + am) * K + k0;
        #pragma unroll
        for (int j = 0; j < 2; ++j) {
            int c = ac + j;
            cpa16(sb + am * 80 + c * 16,           Agh + aoff + c * 8, asz);
            cpa16(sb + G_ALO + am * 80 + c * 16,   Agl + aoff + c * 8, asz);
        }
        size_t boff = (size_t)(k0 + bk) * N + bn;
        #pragma unroll
        for (int j = 0; j < 4; ++j) {
            int c = bc + j;
            cpa16(sb + G_BOFF + bk * 272 + c * 16,            Bgh + boff + c * 8, 16);
            cpa16(sb + G_BOFF + G_BHALF + bk * 272 + c * 16,  Bgl + boff + c * 8, 16);
        }
        CPA_COMMIT();
    };

    load_stage(0, 0);

    for (int kt = 0; kt < KT; ++kt) {
        const int cur = kt & 1;
        if (kt + 1 < KT) { load_stage(cur ^ 1, (kt + 1) * 32); CPA_WAIT1(); }
        else             { CPA_WAIT0(); }
        __syncthreads();

        const uint32_t sb = sbase + (uint32_t)cur * G_STAGE;
        #pragma unroll
        for (int kc = 0; kc < 2; ++kc) {
            uint32_t ahf[2][4], alf[2][4];
            #pragma unroll
            for (int mi = 0; mi < 2; ++mi) {
                uint32_t a = sb + (uint32_t)((warp_m * 32 + mi * 16 + a_row) * 80 + kc * 32 + a_koff);
                ldsm4(ahf[mi], a);
                ldsm4(alf[mi], a + G_ALO);
            }
            #pragma unroll
            for (int np = 0; np < 4; ++np) {
                uint32_t ba = sb + G_BOFF +
                    (uint32_t)((kc * 16 + b_k) * 272 + (warp_n * 64 + np * 16 + b_noff) * 2);
                uint32_t bh4[4], bl4[4];
                ldsm4t(bh4, ba);
                ldsm4t(bl4, ba + G_BHALF);
                uint32_t bH0[2] = { bh4[0], bh4[2] }, bH1[2] = { bh4[1], bh4[3] };
                uint32_t bL0[2] = { bl4[0], bl4[2] }, bL1[2] = { bl4[1], bl4[3] };
                #pragma unroll
                for (int mi = 0; mi < 2; ++mi) {
                    int ni = np * 2;
                    mma16816(acc[mi][ni],     ahf[mi], bH0);
                    mma16816(acc[mi][ni],     alf[mi], bH0);
                    mma16816(acc[mi][ni],     ahf[mi], bL0);
                    mma16816(acc[mi][ni + 1], ahf[mi], bH1);
                    mma16816(acc[mi][ni + 1], alf[mi], bH1);
                    mma16816(acc[mi][ni + 1], ahf[mi], bL1);
                }
            }
        }
        __syncthreads();
    }

    #pragma unroll
    for (int mi = 0; mi < 2; ++mi) {
        #pragma unroll
        for (int ni = 0; ni < 8; ++ni) {
            int row0 = bm + warp_m * 32 + mi * 16 + g;
            int col  = bn + warp_n * 64 + ni * 8 + 2 * t4;
            float2 v0 = make_float2(acc[mi][ni][0], acc[mi][ni][1]);
            float2 v1 = make_float2(acc[mi][ni][2], acc[mi][ni][3]);
            if (bias) {
                float2 bv = *(const float2*)(bias + col);
                v0.x += bv.x; v0.y += bv.y; v1.x += bv.x; v1.y += bv.y;
            }
            if (row0 < M) {
                size_t o0 = (size_t)row0 * N + col;
                if (resid) { float2 r = *(const float2*)(resid + o0); v0.x += r.x; v0.y += r.y; }
                *(float2*)(C + o0) = v0;
            }
            if (row0 + 8 < M) {
                size_t o1 = (size_t)(row0 + 8) * N + col;
                if (resid) { float2 r = *(const float2*)(resid + o1); v1.x += r.x; v1.y += r.y; }
                *(float2*)(C + o1) = v1;
            }
        }
    }
}

// ====================== MMA flash attention (1 or 2 parts, hi/lo bf16 out) ==========
#define AST 72
#define A_QH 0
#define A_QL 4608
#define A_KH 9216
#define A_KL 13824
#define A_VH 18432
#define A_VL 23040
#define ASMEM_BYTES (27648 * 2)

__global__ __launch_bounds__(128, 2)
void attn_mma(const float* __restrict__ Qa, const float* __restrict__ Ka,
              const float* __restrict__ Va,
              const float* __restrict__ Qb, const float* __restrict__ Kb,
              const float* __restrict__ Vb,
              __nv_bfloat16* __restrict__ Oh, __nv_bfloat16* __restrict__ Ol,
              int H, int Sq, int Skv, int ldq, int ldkv, int nparts)
{
    extern __shared__ __nv_bfloat16 ash[];
    const int tid = threadIdx.x, wid = tid >> 5, lane = tid & 31;
    const int g = lane >> 2, t4 = lane & 3;
    const int bh = blockIdx.y, b = bh / H, h = bh % H;
    const int q0 = blockIdx.x * 64;
    const uint32_t sbase = smem_u32(ash);

    const int lq = lane >> 3, li = lane & 7;
    const int lr = (lq & 1) * 8 + li;
    const int lc = (lq >> 1) * 8;

    float res[8][4];
    #pragma unroll
    for (int nt = 0; nt < 8; ++nt)
        #pragma unroll
        for (int j = 0; j < 4; ++j) res[nt][j] = 0.f;

    for (int part = 0; part < nparts; ++part) {
        const float* Q  = part ? Qb : Qa;
        const float* Km = part ? Kb : Ka;
        const float* Vm = part ? Vb : Va;

        __syncthreads();
        #pragma unroll
        for (int it = 0; it < 8; ++it) {
            int idx = tid + it * 128;
            int r = idx >> 4, c4 = idx & 15;
            float4 v = *(const float4*)(Q + (size_t)(b * Sq + q0 + r) * ldq + h * 64 + c4 * 4);
            float x0 = v.x * 0.125f, x1 = v.y * 0.125f, x2 = v.z * 0.125f, x3 = v.w * 0.125f;
            __nv_bfloat16* ph = ash + A_QH + r * AST + c4 * 4;
            __nv_bfloat16* pl = ash + A_QL + r * AST + c4 * 4;
            ((uint32_t*)ph)[0] = pack_hi(x0, x1); ((uint32_t*)ph)[1] = pack_hi(x2, x3);
            ((uint32_t*)pl)[0] = pack_lo(x0, x1); ((uint32_t*)pl)[1] = pack_lo(x2, x3);
        }
        __syncthreads();

        uint32_t qh[4][4], ql[4][4];
        {
            int rr = wid * 16 + lr;
            #pragma unroll
            for (int kc = 0; kc < 4; ++kc) {
                uint32_t a = sbase + 2u * (uint32_t)(rr * AST + kc * 16 + lc);
                ldsm4(qh[kc], a + 2u * A_QH);
                ldsm4(ql[kc], a + 2u * A_QL);
            }
        }

        float o[8][4];
        #pragma unroll
        for (int nt = 0; nt < 8; ++nt)
            #pragma unroll
            for (int j = 0; j < 4; ++j) o[nt][j] = 0.f;
        float mr0 = -1e30f, mr1 = -1e30f, l0 = 0.f, l1 = 0.f;

        const int ntiles = (Skv + 63) / 64;
        for (int jt = 0; jt < ntiles; ++jt) {
            const int kk = jt * 64;
            __syncthreads();
            #pragma unroll
            for (int it = 0; it < 8; ++it) {
                int idx = tid + it * 128;
                int r = idx >> 4, c4 = idx & 15;
                int key = kk + r;
                float4 kv = make_float4(0.f, 0.f, 0.f, 0.f);
                float4 vv = make_float4(0.f, 0.f, 0.f, 0.f);
                if (key < Skv) {
                    size_t off = (size_t)(b * Skv + key) * ldkv + h * 64 + c4 * 4;
                    kv = *(const float4*)(Km + off);
                    vv = *(const float4*)(Vm + off);
                }
                __nv_bfloat16* ph = ash + A_KH + r * AST + c4 * 4;
                __nv_bfloat16* pl = ash + A_KL + r * AST + c4 * 4;
                ((uint32_t*)ph)[0] = pack_hi(kv.x, kv.y); ((uint32_t*)ph)[1] = pack_hi(kv.z, kv.w);
                ((uint32_t*)pl)[0] = pack_lo(kv.x, kv.y); ((uint32_t*)pl)[1] = pack_lo(kv.z, kv.w);
                int d0 = c4 * 4;
                float w[4] = { vv.x, vv.y, vv.z, vv.w };
                #pragma unroll
                for (int j = 0; j < 4; ++j) {
                    float hi = __bfloat162float(__float2bfloat16(w[j]));
                    ash[A_VH + (d0 + j) * AST + r] = __float2bfloat16(w[j]);
                    ash[A_VL + (d0 + j) * AST + r] = __float2bfloat16(w[j] - hi);
                }
            }
            __syncthreads();

            float s[8][4];
            #pragma unroll
            for (int nt = 0; nt < 8; ++nt)
                #pragma unroll
                for (int j = 0; j < 4; ++j) s[nt][j] = 0.f;

            #pragma unroll
            for (int kc = 0; kc < 4; ++kc) {
                #pragma unroll
                for (int np = 0; np < 4; ++np) {
                    uint32_t a = sbase + 2u * (uint32_t)((np * 16 + lr) * AST + kc * 16 + lc);
                    uint32_t kfh[4], kfl[4];
                    ldsm4(kfh, a + 2u * A_KH);
                    ldsm4(kfl, a + 2u * A_KL);
                    uint32_t bAh[2] = { kfh[0], kfh[2] }, bBh[2] = { kfh[1], kfh[3] };
                    uint32_t bAl[2] = { kfl[0], kfl[2] }, bBl[2] = { kfl[1], kfl[3] };
                    mma16816(s[2 * np],     qh[kc], bAh);
                    mma16816(s[2 * np],     ql[kc], bAh);
                    mma16816(s[2 * np],     qh[kc], bAl);
                    mma16816(s[2 * np + 1], qh[kc], bBh);
                    mma16816(s[2 * np + 1], ql[kc], bBh);
                    mma16816(s[2 * np + 1], qh[kc], bBl);
                }
            }

            if (kk + 64 > Skv) {
                #pragma unroll
                for (int nt = 0; nt < 8; ++nt) {
                    int k0c = kk + nt * 8 + 2 * t4;
                    if (k0c >= Skv)     { s[nt][0] = -1e30f; s[nt][2] = -1e30f; }
                    if (k0c + 1 >= Skv) { s[nt][1] = -1e30f; s[nt][3] = -1e30f; }
                }
            }

            float rm0 = -1e30f, rm1 = -1e30f;
            #pragma unroll
            for (int nt = 0; nt < 8; ++nt) {
                rm0 = fmaxf(rm0, fmaxf(s[nt][0], s[nt][1]));
                rm1 = fmaxf(rm1, fmaxf(s[nt][2], s[nt][3]));
            }
            rm0 = fmaxf(rm0, __shfl_xor_sync(0xFFFFFFFFu, rm0, 1));
            rm0 = fmaxf(rm0, __shfl_xor_sync(0xFFFFFFFFu, rm0, 2));
            rm1 = fmaxf(rm1, __shfl_xor_sync(0xFFFFFFFFu, rm1, 1));
            rm1 = fmaxf(rm1, __shfl_xor_sync(0xFFFFFFFFu, rm1, 2));
            float mn0 = fmaxf(mr0, rm0), mn1 = fmaxf(mr1, rm1);
            float c0 = fexp(mr0 - mn0), c1 = fexp(mr1 - mn1);
            mr0 = mn0; mr1 = mn1;
            float ps0 = 0.f, ps1 = 0.f;
            #pragma unroll
            for (int nt = 0; nt < 8; ++nt) {
                s[nt][0] = fexp(s[nt][0] - mn0);
                s[nt][1] = fexp(s[nt][1] - mn0);
                s[nt][2] = fexp(s[nt][2] - mn1);
                s[nt][3] = fexp(s[nt][3] - mn1);
                ps0 += s[nt][0] + s[nt][1];
                ps1 += s[nt][2] + s[nt][3];
            }
            ps0 += __shfl_xor_sync(0xFFFFFFFFu, ps0, 1);
            ps0 += __shfl_xor_sync(0xFFFFFFFFu, ps0, 2);
            ps1 += __shfl_xor_sync(0xFFFFFFFFu, ps1, 1);
            ps1 += __shfl_xor_sync(0xFFFFFFFFu, ps1, 2);
            l0 = l0 * c0 + ps0;
            l1 = l1 * c1 + ps1;
            #pragma unroll
            for (int nt = 0; nt < 8; ++nt) {
                o[nt][0] *= c0; o[nt][1] *= c0;
                o[nt][2] *= c1; o[nt][3] *= c1;
            }

            #pragma unroll
            for (int kc = 0; kc < 4; ++kc) {
                uint32_t pah[4] = {
                    pack_hi(s[2 * kc][0],     s[2 * kc][1]),
                    pack_hi(s[2 * kc][2],     s[2 * kc][3]),
                    pack_hi(s[2 * kc + 1][0], s[2 * kc + 1][1]),
                    pack_hi(s[2 * kc + 1][2], s[2 * kc + 1][3])
                };
                uint32_t pal[4] = {
                    pack_lo(s[2 * kc][0],     s[2 * kc][1]),
                    pack_lo(s[2 * kc][2],     s[2 * kc][3]),
                    pack_lo(s[2 * kc + 1][0], s[2 * kc + 1][1]),
                    pack_lo(s[2 * kc + 1][2], s[2 * kc + 1][3])
                };
                #pragma unroll
                for (int np = 0; np < 4; ++np) {
                    uint32_t a = sbase + 2u * (uint32_t)((np * 16 + lr) * AST + kc * 16 + lc);
                    uint32_t vfh[4], vfl[4];
                    ldsm4(vfh, a + 2u * A_VH);
                    ldsm4(vfl, a + 2u * A_VL);
                    uint32_t bAh[2] = { vfh[0], vfh[2] }, bBh[2] = { vfh[1], vfh[3] };
                    uint32_t bAl[2] = { vfl[0], vfl[2] }, bBl[2] = { vfl[1], vfl[3] };
                    mma16816(o[2 * np],     pah, bAh);
                    mma16816(o[2 * np],     pal, bAh);
                    mma16816(o[2 * np],     pah, bAl);
                    mma16816(o[2 * np + 1], pah, bBh);
                    mma16816(o[2 * np + 1], pal, bBh);
                    mma16816(o[2 * np + 1], pah, bBl);
                }
            }
        }

        float inv0 = 1.f / l0, inv1 = 1.f / l1;
        #pragma unroll
        for (int nt = 0; nt < 8; ++nt) {
            res[nt][0] += o[nt][0] * inv0;
            res[nt][1] += o[nt][1] * inv0;
            res[nt][2] += o[nt][2] * inv1;
            res[nt][3] += o[nt][3] * inv1;
        }
    }

    // write hi/lo bf16 (row stride Dz)
    int row0 = q0 + wid * 16 + g;
    #pragma unroll
    for (int nt = 0; nt < 8; ++nt) {
        int col = nt * 8 + 2 * t4;
        size_t off0 = (size_t)(b * Sq + row0) * Dz + h * 64 + col;
        size_t off1 = (size_t)(b * Sq + row0 + 8) * Dz + h * 64 + col;
        *(uint32_t*)(Oh + off0) = pack_hi(res[nt][0], res[nt][1]);
        *(uint32_t*)(Ol + off0) = pack_lo(res[nt][0], res[nt][1]);
        *(uint32_t*)(Oh + off1) = pack_hi(res[nt][2], res[nt][3]);
        *(uint32_t*)(Ol + off1) = pack_lo(res[nt][2], res[nt][3]);
    }
}

// ---------------- LayerNorm -> hi/lo bf16 ----------------
__global__ void ln_split(const float* __restrict__ x, const float* __restrict__ g,
                         const float* __restrict__ b,
                         __nv_bfloat16* __restrict__ hi, __nv_bfloat16* __restrict__ lo, int D)
{
    int row = blockIdx.x;
    int t = threadIdx.x;
    const float* xp = x + (size_t)row * D;
    float s = 0.f, s2 = 0.f;
    for (int i = t; i < D; i += blockDim.x) { float v = xp[i]; s += v; s2 += v * v; }
    #pragma unroll
    for (int o = 16; o; o >>= 1) {
        s  += __shfl_xor_sync(0xFFFFFFFFu, s,  o);
        s2 += __shfl_xor_sync(0xFFFFFFFFu, s2, o);
    }
    __shared__ float rs[8], rs2[8];
    int w = t >> 5, l = t & 31;
    if (l == 0) { rs[w] = s; rs2[w] = s2; }
    __syncthreads();
    if (t == 0) {
        float a = 0.f, a2 = 0.f;
        int nw = blockDim.x >> 5;
        for (int i = 0; i < nw; ++i) { a += rs[i]; a2 += rs2[i]; }
        rs[0] = a; rs2[0] = a2;
    }
    __syncthreads();
    float mean = rs[0] / (float)D;
    float var  = rs2[0] / (float)D - mean * mean;
    float inv  = rsqrtf(var + 1e-5f);
    for (int i = t; i < D; i += blockDim.x) {
        float v = (xp[i] - mean) * inv * g[i] + b[i];
        __nv_bfloat16 h = __float2bfloat16(v);
        hi[(size_t)row * D + i] = h;
        lo[(size_t)row * D + i] = __float2bfloat16(v - __bfloat162float(h));
    }
}

// ---------------- fp32 -> hi/lo bf16 (contiguous) ----------------
__global__ void split_kernel(const float* __restrict__ x,
                             __nv_bfloat16* __restrict__ hi, __nv_bfloat16* __restrict__ lo,
                             int n4)
{
    int idx = blockIdx.x * blockDim.x + threadIdx.x;
    if (idx >= n4) return;
    float4 v = *(const float4*)(x + (size_t)idx * 4);
    uint32_t* ph = (uint32_t*)(hi + (size_t)idx * 4);
    uint32_t* pl = (uint32_t*)(lo + (size_t)idx * 4);
    ph[0] = pack_hi(v.x, v.y); ph[1] = pack_hi(v.z, v.w);
    pl[0] = pack_lo(v.x, v.y); pl[1] = pack_lo(v.z, v.w);
}

// ---------------- fp32 [K,N] -> hi/lo bf16 written at [k*ldo + off + j] ------------
__global__ void split_strided(const float* __restrict__ x,
                              __nv_bfloat16* __restrict__ hi, __nv_bfloat16* __restrict__ lo,
                              int Kr, int Nc, int ldo, int off)
{
    int idx = blockIdx.x * blockDim.x + threadIdx.x;
    int n4row = Nc / 4;
    if (idx >= Kr * n4row) return;
    int k = idx / n4row, c4 = idx - k * n4row;
    float4 v = *(const float4*)(x + (size_t)k * Nc + c4 * 4);
    size_t ob = (size_t)k * ldo + off + c4 * 4;
    uint32_t* ph = (uint32_t*)(hi + ob);
    uint32_t* pl = (uint32_t*)(lo + ob);
    ph[0] = pack_hi(v.x, v.y); ph[1] = pack_hi(v.z, v.w);
    pl[0] = pack_lo(v.x, v.y); pl[1] = pack_lo(v.z, v.w);
}

// ---------------- GEGLU -> hi/lo bf16 ----------------
__global__ void geglu_split(const float* __restrict__ G,
                            __nv_bfloat16* __restrict__ hi, __nv_bfloat16* __restrict__ lo,
                            int M, int DFF)
{
    int idx = blockIdx.x * blockDim.x + threadIdx.x;
    if (idx >= M * DFF) return;
    int m = idx / DFF, j = idx - m * DFF;
    size_t base = (size_t)m * (2 * DFF);
    float a = G[base + j];
    float x = G[base + DFF + j];
    float x3 = x * x * x;
    float gl = 0.5f * x * (1.f + tanhf(0.7978845608028654f * (x + 0.044715f * x3)));
    float v = a * gl;
    __nv_bfloat16 h = __float2bfloat16(v);
    hi[idx] = h;
    lo[idx] = __float2bfloat16(v - __bfloat162float(h));
}

// ---------------- host orchestration ----------------
static inline void launch_gemm(const __nv_bfloat16* Ah, const __nv_bfloat16* Al,
                               const __nv_bfloat16* Bh, const __nv_bfloat16* Bl,
                               const float* bias, const float* resid,
                               float* C, int M, int N, int K)
{
    dim3 grid(N / 128, (M + 63) / 64);
    gemm_bf<<<grid, 128, G_SMEM>>>(Ah, Al, Bh, Bl, bias, resid, C, M, N, K);
}
static inline void launch_split(const float* x, __nv_bfloat16* h, __nv_bfloat16* l, size_t n)
{
    int n4 = (int)(n / 4);
    split_kernel<<<(n4 + 255) / 256, 256>>>(x, h, l, n4);
}
static inline void launch_split_strided(const float* x, __nv_bfloat16* h, __nv_bfloat16* l,
                                        int Kr, int Nc, int ldo, int off)
{
    int n = Kr * (Nc / 4);
    split_strided<<<(n + 255) / 256, 256>>>(x, h, l, Kr, Nc, ldo, off);
}

extern "C" void kernel_launch(void* const* d_in, const int* in_sizes, int n_in,
                              void* d_out, int out_size)
{
    const float* h1   = (const float*)d_in[0];
    const float* h2   = (const float*)d_in[1];
    const float* enc  = (const float*)d_in[2];
    const float* wq   = (const float*)d_in[3];
    const float* wk   = (const float*)d_in[4];
    const float* wv   = (const float*)d_in[5];
    const float* wqc  = (const float*)d_in[6];
    const float* wo   = (const float*)d_in[7];
    const float* bo   = (const float*)d_in[8];
    const float* ln1g = (const float*)d_in[9];
    const float* ln1b = (const float*)d_in[10];
    const float* ln2g = (const float*)d_in[11];
    const float* ln2b = (const float*)d_in[12];
    const float* w2q  = (const float*)d_in[13];
    const float* w2k  = (const float*)d_in[14];
    const float* w2v  = (const float*)d_in[15];
    const float* w2o  = (const float*)d_in[16];
    const float* b2o  = (const float*)d_in[17];
    const float* wff1 = (const float*)d_in[18];
    const float* bff1 = (const float*)d_in[19];
    const float* wff2 = (const float*)d_in[20];
    const float* bff2 = (const float*)d_in[21];

    float* H1 = (float*)d_out;
    float* H2 = H1 + NACT;

    static int attr_set = 0;
    if (!attr_set) {
        cudaFuncSetAttribute(gemm_bf,  cudaFuncAttributeMaxDynamicSharedMemorySize, G_SMEM);
        cudaFuncSetAttribute(attn_mma, cudaFuncAttributeMaxDynamicSharedMemorySize, ASMEM_BYTES);
        attr_set = 1;
    }

    float *q1, *q2, *ffp, *qkv2;
    __nv_bfloat16 *a1h, *a1l, *a2h, *a2l, *t1h, *t1l, *t2h, *t2l;
    __nv_bfloat16 *eh, *el, *fh, *fl, *wh, *wl;
    cudaGetSymbolAddress((void**)&q1,   g_q1);
    cudaGetSymbolAddress((void**)&q2,   g_q2);
    cudaGetSymbolAddress((void**)&ffp,  g_ffp);
    cudaGetSymbolAddress((void**)&qkv2, g_qkv2);
    cudaGetSymbolAddress((void**)&a1h, sA1h); cudaGetSymbolAddress((void**)&a1l, sA1l);
    cudaGetSymbolAddress((void**)&a2h, sA2h); cudaGetSymbolAddress((void**)&a2l, sA2l);
    cudaGetSymbolAddress((void**)&t1h, sT1h); cudaGetSymbolAddress((void**)&t1l, sT1l);
    cudaGetSymbolAddress((void**)&t2h, sT2h); cudaGetSymbolAddress((void**)&t2l, sT2l);
    cudaGetSymbolAddress((void**)&eh,  sEh);  cudaGetSymbolAddress((void**)&el,  sEl);
    cudaGetSymbolAddress((void**)&fh,  sFh);  cudaGetSymbolAddress((void**)&fl,  sFl);
    cudaGetSymbolAddress((void**)&wh,  sWh);  cudaGetSymbolAddress((void**)&wl,  sWl);

    const size_t DD = (size_t)Dz * Dz;
    // fused QKV activations: qkv1 in first half of g_ffp (M1 x 4096), qkv2 separate
    float* qkv1 = ffp;
    // enc KV fused buffers (phase B; ffp is free again by then)
    float* kvE1 = ffp;                                   // MEnc x 2048
    float* kvE2 = ffp + (size_t)MEnc * 2048;

    // ---- Phase A: LN1 + fused QKV + dual attention ----
    ln_split<<<M1, 256>>>(h1, ln1g,      ln1b,      a1h, a1l, Dz);
    ln_split<<<M1, 256>>>(h2, ln1g + Dz, ln1b + Dz, a2h, a2l, Dz);

    // stream1 fused weight [Dz, 4096]: q|k|v|qc
    launch_split_strided(wq,  wh, wl, Dz, Dz, 4096, 0);
    launch_split_strided(wk,  wh, wl, Dz, Dz, 4096, 1024);
    launch_split_strided(wv,  wh, wl, Dz, Dz, 4096, 2048);
    launch_split_strided(wqc, wh, wl, Dz, Dz, 4096, 3072);
    launch_gemm(a1h, a1l, wh, wl, nullptr, nullptr, qkv1, M1, 4096, Dz);

    __nv_bfloat16* wh2 = wh + (size_t)Dz * 4096;
    __nv_bfloat16* wl2 = wl + (size_t)Dz * 4096;
    launch_split_strided(wq  + DD, wh2, wl2, Dz, Dz, 4096, 0);
    launch_split_strided(wk  + DD, wh2, wl2, Dz, Dz, 4096, 1024);
    launch_split_strided(wv  + DD, wh2, wl2, Dz, Dz, 4096, 2048);
    launch_split_strided(wqc + DD, wh2, wl2, Dz, Dz, 4096, 3072);
    launch_gemm(a2h, a2l, wh2, wl2, nullptr, nullptr, qkv2, M1, 4096, Dz);

    dim3 agrid(Sz / 64, Bz * Hz);
    // a1 = attn(q1,k1,v1) + attn(qc1,k2,v2)
    attn_mma<<<agrid, 128, ASMEM_BYTES>>>(qkv1, qkv1 + 1024, qkv1 + 2048,
                                          qkv1 + 3072, qkv2 + 1024, qkv2 + 2048,
                                          t1h, t1l, Hz, Sz, Sz, 4096, 4096, 2);
    // a2 = attn(q2,k2,v2) + attn(qc2,k1,v1)
    attn_mma<<<agrid, 128, ASMEM_BYTES>>>(qkv2, qkv2 + 1024, qkv2 + 2048,
                                          qkv2 + 3072, qkv1 + 1024, qkv1 + 2048,
                                          t2h, t2l, Hz, Sz, Sz, 4096, 4096, 2);

    launch_split(wo,      wh, wl, DD);
    launch_gemm(t1h, t1l, wh, wl, bo,      h1, H1, M1, Dz, Dz);
    launch_split(wo + DD, wh, wl, DD);
    launch_gemm(t2h, t2l, wh, wl, bo + Dz, h2, H2, M1, Dz, Dz);

    // ---- Phase B: LN2 + cross attention to encoder ----
    ln_split<<<M1, 256>>>(H1, ln2g,      ln2b,      a1h, a1l, Dz);
    ln_split<<<M1, 256>>>(H2, ln2g + Dz, ln2b + Dz, a2h, a2l, Dz);

    launch_split(w2q,      wh, wl, DD);
    launch_gemm(a1h, a1l, wh, wl, nullptr, nullptr, q1, M1, Dz, Dz);
    launch_split(w2q + DD, wh, wl, DD);
    launch_gemm(a2h, a2l, wh, wl, nullptr, nullptr, q2, M1, Dz, Dz);

    launch_split(enc, eh, el, (size_t)MEnc * DEz);
    // fused [DEz, 2048]: k|v
    launch_split_strided(w2k, wh, wl, DEz, Dz, 2048, 0);
    launch_split_strided(w2v, wh, wl, DEz, Dz, 2048, 1024);
    launch_gemm(eh, el, wh, wl, nullptr, nullptr, kvE1, MEnc, 2048, DEz);
    launch_split_strided(w2k + (size_t)DEz * Dz, wh2, wl2, DEz, Dz, 2048, 0);
    launch_split_strided(w2v + (size_t)DEz * Dz, wh2, wl2, DEz, Dz, 2048, 1024);
    launch_gemm(eh, el, wh2, wl2, nullptr, nullptr, kvE2, MEnc, 2048, DEz);

    attn_mma<<<agrid, 128, ASMEM_BYTES>>>(q1, kvE1, kvE1 + 1024,
                                          nullptr, nullptr, nullptr,
                                          t1h, t1l, Hz, Sz, SEz, 1024, 2048, 1);
    attn_mma<<<agrid, 128, ASMEM_BYTES>>>(q2, kvE2, kvE2 + 1024,
                                          nullptr, nullptr, nullptr,
                                          t2h, t2l, Hz, Sz, SEz, 1024, 2048, 1);

    launch_split(w2o,      wh, wl, DD);
    launch_gemm(t1h, t1l, wh, wl, b2o,      H1, H1, M1, Dz, Dz);
    launch_split(w2o + DD, wh, wl, DD);
    launch_gemm(t2h, t2l, wh, wl, b2o + Dz, H2, H2, M1, Dz, Dz);

    // ---- Phase C: GEGLU feed-forward ----
    int nGeglu = M1 * DFFz;
    launch_split(wff1, wh, wl, (size_t)Dz * 2 * DFFz);
    launch_gemm(a1h, a1l, wh, wl, bff1, nullptr, ffp, M1, 2 * DFFz, Dz);
    geglu_split<<<(nGeglu + 255) / 256, 256>>>(ffp, fh, fl, M1, DFFz);
    launch_split(wff2, wh, wl, (size_t)DFFz * Dz);
    launch_gemm(fh, fl, wh, wl, bff2, H1, H1, M1, Dz, DFFz);

    launch_split(wff1 + (size_t)Dz * 2 * DFFz, wh, wl, (size_t)Dz * 2 * DFFz);
    launch_gemm(a2h, a2l, wh, wl, bff1 + 2 * DFFz, nullptr, ffp, M1, 2 * DFFz, Dz);
    geglu_split<<<(nGeglu + 255) / 256, 256>>>(ffp, fh, fl, M1, DFFz);
    launch_split(wff2 + (size_t)DFFz * Dz, wh, wl, (size_t)DFFz * Dz);
    launch_gemm(fh, fl, wh, wl, bff2 + Dz, H2, H2, M1, Dz, DFFz);
}

// round 11
// speedup vs baseline: 1.2426x; 1.2426x over previous
#include <cuda_runtime.h>
#include <cuda_bf16.h>
#include <math.h>
#include <stdint.h>

// Problem constants
#define Bz   4
#define Sz   1024
#define Dz   1024
#define Hz   16
#define SEz  77
#define DEz  768
#define DFFz 4096
#define M1   (Bz * Sz)          // 4096
#define MEnc (Bz * SEz)         // 308
#define NACT ((size_t)M1 * Dz)  // 4,194,304

// ---------------- scratch (static __device__, allocation-free) ----------------
__device__ float g_q1[NACT], g_q2[NACT];
__device__ float g_ffp[(size_t)M1 * 2 * DFFz];   // also hosts fused qkv / enc-kv staging
__device__ float g_qkv2[(size_t)M1 * 4 * Dz];

// bf16 hi/lo operand buffers
__device__ __nv_bfloat16 sA1h[NACT], sA1l[NACT], sA2h[NACT], sA2l[NACT];
__device__ __nv_bfloat16 sT1h[NACT], sT1l[NACT], sT2h[NACT], sT2l[NACT];
__device__ __nv_bfloat16 sEh[(size_t)MEnc * DEz], sEl[(size_t)MEnc * DEz];
__device__ __nv_bfloat16 sFh[(size_t)M1 * DFFz], sFl[(size_t)M1 * DFFz];
__device__ __nv_bfloat16 sWh[(size_t)Dz * 2 * DFFz], sWl[(size_t)Dz * 2 * DFFz];

// ====================== common helpers ======================
__device__ __forceinline__ uint32_t smem_u32(const void* p) {
    uint32_t a;
    asm("{ .reg .u64 t; cvta.to.shared.u64 t, %1; cvt.u32.u64 %0, t; }" : "=r"(a) : "l"(p));
    return a;
}
__device__ __forceinline__ void mma16816(float* c, const uint32_t* a, const uint32_t* b) {
    asm volatile(
        "mma.sync.aligned.m16n8k16.row.col.f32.bf16.bf16.f32 "
        "{%0,%1,%2,%3}, {%4,%5,%6,%7}, {%8,%9}, {%0,%1,%2,%3};"
        : "+f"(c[0]), "+f"(c[1]), "+f"(c[2]), "+f"(c[3])
        : "r"(a[0]), "r"(a[1]), "r"(a[2]), "r"(a[3]), "r"(b[0]), "r"(b[1]));
}
__device__ __forceinline__ void ldsm4(uint32_t* r, uint32_t addr) {
    asm volatile("ldmatrix.sync.aligned.m8n8.x4.shared.b16 {%0,%1,%2,%3}, [%4];"
        : "=r"(r[0]), "=r"(r[1]), "=r"(r[2]), "=r"(r[3]) : "r"(addr));
}
__device__ __forceinline__ void ldsm4t(uint32_t* r, uint32_t addr) {
    asm volatile("ldmatrix.sync.aligned.m8n8.x4.trans.shared.b16 {%0,%1,%2,%3}, [%4];"
        : "=r"(r[0]), "=r"(r[1]), "=r"(r[2]), "=r"(r[3]) : "r"(addr));
}
__device__ __forceinline__ void cpa16(uint32_t saddr, const void* g, int src_sz) {
    asm volatile("cp.async.ca.shared.global [%0], [%1], 16, %2;"
        :: "r"(saddr), "l"(g), "r"(src_sz));
}
#define CPA_COMMIT() asm volatile("cp.async.commit_group;" ::: "memory")
#define CPA_WAIT0()  asm volatile("cp.async.wait_group 0;" ::: "memory")
#define CPA_WAIT1()  asm volatile("cp.async.wait_group 1;" ::: "memory")

__device__ __forceinline__ uint32_t pack_hi(float x, float y) {
    __nv_bfloat162 h(__float2bfloat16(x), __float2bfloat16(y));
    return *(uint32_t*)&h;
}
__device__ __forceinline__ uint32_t pack_lo(float x, float y) {
    float hx = __bfloat162float(__float2bfloat16(x));
    float hy = __bfloat162float(__float2bfloat16(y));
    __nv_bfloat162 l(__float2bfloat16(x - hx), __float2bfloat16(y - hy));
    return *(uint32_t*)&l;
}
// fast exp on FMA pipe (rel err ~2e-6)
__device__ __forceinline__ float fexp(float x) {
    float y = x * 1.4426950408889634f;
    float n = rintf(y);
    float f = y - n;
    float p = 1.5403530e-4f;
    p = fmaf(p, f, 0.0013333558f);
    p = fmaf(p, f, 0.0096181291f);
    p = fmaf(p, f, 0.0555041087f);
    p = fmaf(p, f, 0.2402265070f);
    p = fmaf(p, f, 0.6931471806f);
    p = fmaf(p, f, 1.0f);
    int e = (int)n;
    float r = __int_as_float((e + 127) << 23) * p;
    return (x < -80.f) ? 0.f : r;
}

// ====================== bf16 hi/lo GEMM (R6 proven: BM=128, BN=128, BK=32, 256 thr) ===
#define G_AHALF 10240
#define G_BOFF  20480
#define G_BHALF 8704
#define G_STAGE 37888
#define G_SMEM  (2 * G_STAGE)   // 75776

__global__ __launch_bounds__(256, 2)
void gemm_bf(const __nv_bfloat16* __restrict__ Agh, const __nv_bfloat16* __restrict__ Agl,
             const __nv_bfloat16* __restrict__ Bgh, const __nv_bfloat16* __restrict__ Bgl,
             const float* __restrict__ bias, const float* __restrict__ resid,
             float* __restrict__ C, int M, int N, int K)
{
    extern __shared__ char smraw[];
    const uint32_t sbase = smem_u32(smraw);
    const int tid = threadIdx.x, wid = tid >> 5, lane = tid & 31;
    const int g = lane >> 2, t4 = lane & 3;
    const int warp_m = wid >> 1, warp_n = wid & 1;
    const int bm = blockIdx.y * 128, bn = blockIdx.x * 128;

    // ldmatrix address lanes
    const int r8 = lane & 7, q = lane >> 3;
    const int a_row  = r8 + (q & 1) * 8;
    const int a_koff = (q >> 1) * 16;          // bytes
    const int b_k    = r8 + (q >> 1) * 8;
    const int b_noff = (q & 1) * 8;            // elems

    // loader lanes
    const int am = tid >> 1, ac = (tid & 1) * 2;
    const int bk = tid >> 3, bc = (tid & 7) * 2;
    const bool aok = (bm + am) < M;
    const int asz = aok ? 16 : 0;

    float acc[2][8][4];
    #pragma unroll
    for (int mi = 0; mi < 2; ++mi)
        #pragma unroll
        for (int ni = 0; ni < 8; ++ni)
            #pragma unroll
            for (int j = 0; j < 4; ++j) acc[mi][ni][j] = 0.f;

    const int KT = K / 32;

    auto load_stage = [&](int s, int k0) {
        uint32_t sb = sbase + (uint32_t)s * G_STAGE;
        size_t aoff = (size_t)(bm + am) * K + k0;
        #pragma unroll
        for (int j = 0; j < 2; ++j) {
            int c = ac + j;
            cpa16(sb + am * 80 + c * 16,            Agh + aoff + c * 8, asz);
            cpa16(sb + G_AHALF + am * 80 + c * 16,  Agl + aoff + c * 8, asz);
        }
        size_t boff = (size_t)(k0 + bk) * N + bn;
        #pragma unroll
        for (int j = 0; j < 2; ++j) {
            int c = bc + j;
            cpa16(sb + G_BOFF + bk * 272 + c * 16,            Bgh + boff + c * 8, 16);
            cpa16(sb + G_BOFF + G_BHALF + bk * 272 + c * 16,  Bgl + boff + c * 8, 16);
        }
        CPA_COMMIT();
    };

    load_stage(0, 0);

    for (int kt = 0; kt < KT; ++kt) {
        const int cur = kt & 1;
        if (kt + 1 < KT) { load_stage(cur ^ 1, (kt + 1) * 32); CPA_WAIT1(); }
        else             { CPA_WAIT0(); }
        __syncthreads();

        const uint32_t sb = sbase + (uint32_t)cur * G_STAGE;
        #pragma unroll
        for (int kc = 0; kc < 2; ++kc) {
            uint32_t ahf[2][4], alf[2][4];
            #pragma unroll
            for (int mi = 0; mi < 2; ++mi) {
                uint32_t a = sb + (uint32_t)((warp_m * 32 + mi * 16 + a_row) * 80 + kc * 32 + a_koff);
                ldsm4(ahf[mi], a);
                ldsm4(alf[mi], a + G_AHALF);
            }
            #pragma unroll
            for (int np = 0; np < 4; ++np) {
                uint32_t ba = sb + G_BOFF +
                    (uint32_t)((kc * 16 + b_k) * 272 + (warp_n * 64 + np * 16 + b_noff) * 2);
                uint32_t bh4[4], bl4[4];
                ldsm4t(bh4, ba);
                ldsm4t(bl4, ba + G_BHALF);
                uint32_t bH0[2] = { bh4[0], bh4[2] }, bH1[2] = { bh4[1], bh4[3] };
                uint32_t bL0[2] = { bl4[0], bl4[2] }, bL1[2] = { bl4[1], bl4[3] };
                #pragma unroll
                for (int mi = 0; mi < 2; ++mi) {
                    int ni = np * 2;
                    mma16816(acc[mi][ni],     ahf[mi], bH0);
                    mma16816(acc[mi][ni],     alf[mi], bH0);
                    mma16816(acc[mi][ni],     ahf[mi], bL0);
                    mma16816(acc[mi][ni + 1], ahf[mi], bH1);
                    mma16816(acc[mi][ni + 1], alf[mi], bH1);
                    mma16816(acc[mi][ni + 1], ahf[mi], bL1);
                }
            }
        }
        __syncthreads();
    }

    #pragma unroll
    for (int mi = 0; mi < 2; ++mi) {
        #pragma unroll
        for (int ni = 0; ni < 8; ++ni) {
            int row0 = bm + warp_m * 32 + mi * 16 + g;
            int col  = bn + warp_n * 64 + ni * 8 + 2 * t4;
            float2 v0 = make_float2(acc[mi][ni][0], acc[mi][ni][1]);
            float2 v1 = make_float2(acc[mi][ni][2], acc[mi][ni][3]);
            if (bias) {
                float2 bv = *(const float2*)(bias + col);
                v0.x += bv.x; v0.y += bv.y; v1.x += bv.x; v1.y += bv.y;
            }
            if (row0 < M) {
                size_t o0 = (size_t)row0 * N + col;
                if (resid) { float2 r = *(const float2*)(resid + o0); v0.x += r.x; v0.y += r.y; }
                *(float2*)(C + o0) = v0;
            }
            if (row0 + 8 < M) {
                size_t o1 = (size_t)(row0 + 8) * N + col;
                if (resid) { float2 r = *(const float2*)(resid + o1); v1.x += r.x; v1.y += r.y; }
                *(float2*)(C + o1) = v1;
            }
        }
    }
}

// ====================== MMA flash attention (1 or 2 parts, hi/lo bf16 out) ==========
#define AST 72
#define A_QH 0
#define A_QL 4608
#define A_KH 9216
#define A_KL 13824
#define A_VH 18432
#define A_VL 23040
#define ASMEM_BYTES (27648 * 2)

__global__ __launch_bounds__(128, 2)
void attn_mma(const float* __restrict__ Qa, const float* __restrict__ Ka,
              const float* __restrict__ Va,
              const float* __restrict__ Qb, const float* __restrict__ Kb,
              const float* __restrict__ Vb,
              __nv_bfloat16* __restrict__ Oh, __nv_bfloat16* __restrict__ Ol,
              int H, int Sq, int Skv, int ldq, int ldkv, int nparts)
{
    extern __shared__ __nv_bfloat16 ash[];
    const int tid = threadIdx.x, wid = tid >> 5, lane = tid & 31;
    const int g = lane >> 2, t4 = lane & 3;
    const int bh = blockIdx.y, b = bh / H, h = bh % H;
    const int q0 = blockIdx.x * 64;
    const uint32_t sbase = smem_u32(ash);

    const int lq = lane >> 3, li = lane & 7;
    const int lr = (lq & 1) * 8 + li;
    const int lc = (lq >> 1) * 8;

    float res[8][4];
    #pragma unroll
    for (int nt = 0; nt < 8; ++nt)
        #pragma unroll
        for (int j = 0; j < 4; ++j) res[nt][j] = 0.f;

    for (int part = 0; part < nparts; ++part) {
        const float* Q  = part ? Qb : Qa;
        const float* Km = part ? Kb : Ka;
        const float* Vm = part ? Vb : Va;

        __syncthreads();
        #pragma unroll
        for (int it = 0; it < 8; ++it) {
            int idx = tid + it * 128;
            int r = idx >> 4, c4 = idx & 15;
            float4 v = *(const float4*)(Q + (size_t)(b * Sq + q0 + r) * ldq + h * 64 + c4 * 4);
            float x0 = v.x * 0.125f, x1 = v.y * 0.125f, x2 = v.z * 0.125f, x3 = v.w * 0.125f;
            __nv_bfloat16* ph = ash + A_QH + r * AST + c4 * 4;
            __nv_bfloat16* pl = ash + A_QL + r * AST + c4 * 4;
            ((uint32_t*)ph)[0] = pack_hi(x0, x1); ((uint32_t*)ph)[1] = pack_hi(x2, x3);
            ((uint32_t*)pl)[0] = pack_lo(x0, x1); ((uint32_t*)pl)[1] = pack_lo(x2, x3);
        }
        __syncthreads();

        uint32_t qh[4][4], ql[4][4];
        {
            int rr = wid * 16 + lr;
            #pragma unroll
            for (int kc = 0; kc < 4; ++kc) {
                uint32_t a = sbase + 2u * (uint32_t)(rr * AST + kc * 16 + lc);
                ldsm4(qh[kc], a + 2u * A_QH);
                ldsm4(ql[kc], a + 2u * A_QL);
            }
        }

        float o[8][4];
        #pragma unroll
        for (int nt = 0; nt < 8; ++nt)
            #pragma unroll
            for (int j = 0; j < 4; ++j) o[nt][j] = 0.f;
        float mr0 = -1e30f, mr1 = -1e30f, l0 = 0.f, l1 = 0.f;

        const int ntiles = (Skv + 63) / 64;
        for (int jt = 0; jt < ntiles; ++jt) {
            const int kk = jt * 64;
            __syncthreads();
            #pragma unroll
            for (int it = 0; it < 8; ++it) {
                int idx = tid + it * 128;
                int r = idx >> 4, c4 = idx & 15;
                int key = kk + r;
                float4 kv = make_float4(0.f, 0.f, 0.f, 0.f);
                float4 vv = make_float4(0.f, 0.f, 0.f, 0.f);
                if (key < Skv) {
                    size_t off = (size_t)(b * Skv + key) * ldkv + h * 64 + c4 * 4;
                    kv = *(const float4*)(Km + off);
                    vv = *(const float4*)(Vm + off);
                }
                __nv_bfloat16* ph = ash + A_KH + r * AST + c4 * 4;
                __nv_bfloat16* pl = ash + A_KL + r * AST + c4 * 4;
                ((uint32_t*)ph)[0] = pack_hi(kv.x, kv.y); ((uint32_t*)ph)[1] = pack_hi(kv.z, kv.w);
                ((uint32_t*)pl)[0] = pack_lo(kv.x, kv.y); ((uint32_t*)pl)[1] = pack_lo(kv.z, kv.w);
                int d0 = c4 * 4;
                float w[4] = { vv.x, vv.y, vv.z, vv.w };
                #pragma unroll
                for (int j = 0; j < 4; ++j) {
                    float hi = __bfloat162float(__float2bfloat16(w[j]));
                    ash[A_VH + (d0 + j) * AST + r] = __float2bfloat16(w[j]);
                    ash[A_VL + (d0 + j) * AST + r] = __float2bfloat16(w[j] - hi);
                }
            }
            __syncthreads();

            float s[8][4];
            #pragma unroll
            for (int nt = 0; nt < 8; ++nt)
                #pragma unroll
                for (int j = 0; j < 4; ++j) s[nt][j] = 0.f;

            #pragma unroll
            for (int kc = 0; kc < 4; ++kc) {
                #pragma unroll
                for (int np = 0; np < 4; ++np) {
                    uint32_t a = sbase + 2u * (uint32_t)((np * 16 + lr) * AST + kc * 16 + lc);
                    uint32_t kfh[4], kfl[4];
                    ldsm4(kfh, a + 2u * A_KH);
                    ldsm4(kfl, a + 2u * A_KL);
                    uint32_t bAh[2] = { kfh[0], kfh[2] }, bBh[2] = { kfh[1], kfh[3] };
                    uint32_t bAl[2] = { kfl[0], kfl[2] }, bBl[2] = { kfl[1], kfl[3] };
                    mma16816(s[2 * np],     qh[kc], bAh);
                    mma16816(s[2 * np],     ql[kc], bAh);
                    mma16816(s[2 * np],     qh[kc], bAl);
                    mma16816(s[2 * np + 1], qh[kc], bBh);
                    mma16816(s[2 * np + 1], ql[kc], bBh);
                    mma16816(s[2 * np + 1], qh[kc], bBl);
                }
            }

            if (kk + 64 > Skv) {
                #pragma unroll
                for (int nt = 0; nt < 8; ++nt) {
                    int k0c = kk + nt * 8 + 2 * t4;
                    if (k0c >= Skv)     { s[nt][0] = -1e30f; s[nt][2] = -1e30f; }
                    if (k0c + 1 >= Skv) { s[nt][1] = -1e30f; s[nt][3] = -1e30f; }
                }
            }

            float rm0 = -1e30f, rm1 = -1e30f;
            #pragma unroll
            for (int nt = 0; nt < 8; ++nt) {
                rm0 = fmaxf(rm0, fmaxf(s[nt][0], s[nt][1]));
                rm1 = fmaxf(rm1, fmaxf(s[nt][2], s[nt][3]));
            }
            rm0 = fmaxf(rm0, __shfl_xor_sync(0xFFFFFFFFu, rm0, 1));
            rm0 = fmaxf(rm0, __shfl_xor_sync(0xFFFFFFFFu, rm0, 2));
            rm1 = fmaxf(rm1, __shfl_xor_sync(0xFFFFFFFFu, rm1, 1));
            rm1 = fmaxf(rm1, __shfl_xor_sync(0xFFFFFFFFu, rm1, 2));
            float mn0 = fmaxf(mr0, rm0), mn1 = fmaxf(mr1, rm1);
            float c0 = fexp(mr0 - mn0), c1 = fexp(mr1 - mn1);
            mr0 = mn0; mr1 = mn1;
            float ps0 = 0.f, ps1 = 0.f;
            #pragma unroll
            for (int nt = 0; nt < 8; ++nt) {
                s[nt][0] = fexp(s[nt][0] - mn0);
                s[nt][1] = fexp(s[nt][1] - mn0);
                s[nt][2] = fexp(s[nt][2] - mn1);
                s[nt][3] = fexp(s[nt][3] - mn1);
                ps0 += s[nt][0] + s[nt][1];
                ps1 += s[nt][2] + s[nt][3];
            }
            ps0 += __shfl_xor_sync(0xFFFFFFFFu, ps0, 1);
            ps0 += __shfl_xor_sync(0xFFFFFFFFu, ps0, 2);
            ps1 += __shfl_xor_sync(0xFFFFFFFFu, ps1, 1);
            ps1 += __shfl_xor_sync(0xFFFFFFFFu, ps1, 2);
            l0 = l0 * c0 + ps0;
            l1 = l1 * c1 + ps1;
            #pragma unroll
            for (int nt = 0; nt < 8; ++nt) {
                o[nt][0] *= c0; o[nt][1] *= c0;
                o[nt][2] *= c1; o[nt][3] *= c1;
            }

            #pragma unroll
            for (int kc = 0; kc < 4; ++kc) {
                uint32_t pah[4] = {
                    pack_hi(s[2 * kc][0],     s[2 * kc][1]),
                    pack_hi(s[2 * kc][2],     s[2 * kc][3]),
                    pack_hi(s[2 * kc + 1][0], s[2 * kc + 1][1]),
                    pack_hi(s[2 * kc + 1][2], s[2 * kc + 1][3])
                };
                uint32_t pal[4] = {
                    pack_lo(s[2 * kc][0],     s[2 * kc][1]),
                    pack_lo(s[2 * kc][2],     s[2 * kc][3]),
                    pack_lo(s[2 * kc + 1][0], s[2 * kc + 1][1]),
                    pack_lo(s[2 * kc + 1][2], s[2 * kc + 1][3])
                };
                #pragma unroll
                for (int np = 0; np < 4; ++np) {
                    uint32_t a = sbase + 2u * (uint32_t)((np * 16 + lr) * AST + kc * 16 + lc);
                    uint32_t vfh[4], vfl[4];
                    ldsm4(vfh, a + 2u * A_VH);
                    ldsm4(vfl, a + 2u * A_VL);
                    uint32_t bAh[2] = { vfh[0], vfh[2] }, bBh[2] = { vfh[1], vfh[3] };
                    uint32_t bAl[2] = { vfl[0], vfl[2] }, bBl[2] = { vfl[1], vfl[3] };
                    mma16816(o[2 * np],     pah, bAh);
                    mma16816(o[2 * np],     pal, bAh);
                    mma16816(o[2 * np],     pah, bAl);
                    mma16816(o[2 * np + 1], pah, bBh);
                    mma16816(o[2 * np + 1], pal, bBh);
                    mma16816(o[2 * np + 1], pah, bBl);
                }
            }
        }

        float inv0 = 1.f / l0, inv1 = 1.f / l1;
        #pragma unroll
        for (int nt = 0; nt < 8; ++nt) {
            res[nt][0] += o[nt][0] * inv0;
            res[nt][1] += o[nt][1] * inv0;
            res[nt][2] += o[nt][2] * inv1;
            res[nt][3] += o[nt][3] * inv1;
        }
    }

    // write hi/lo bf16 (row stride Dz)
    int row0 = q0 + wid * 16 + g;
    #pragma unroll
    for (int nt = 0; nt < 8; ++nt) {
        int col = nt * 8 + 2 * t4;
        size_t off0 = (size_t)(b * Sq + row0) * Dz + h * 64 + col;
        size_t off1 = (size_t)(b * Sq + row0 + 8) * Dz + h * 64 + col;
        *(uint32_t*)(Oh + off0) = pack_hi(res[nt][0], res[nt][1]);
        *(uint32_t*)(Ol + off0) = pack_lo(res[nt][0], res[nt][1]);
        *(uint32_t*)(Oh + off1) = pack_hi(res[nt][2], res[nt][3]);
        *(uint32_t*)(Ol + off1) = pack_lo(res[nt][2], res[nt][3]);
    }
}

// ---------------- LayerNorm -> hi/lo bf16 ----------------
__global__ void ln_split(const float* __restrict__ x, const float* __restrict__ g,
                         const float* __restrict__ b,
                         __nv_bfloat16* __restrict__ hi, __nv_bfloat16* __restrict__ lo, int D)
{
    int row = blockIdx.x;
    int t = threadIdx.x;
    const float* xp = x + (size_t)row * D;
    float s = 0.f, s2 = 0.f;
    for (int i = t; i < D; i += blockDim.x) { float v = xp[i]; s += v; s2 += v * v; }
    #pragma unroll
    for (int o = 16; o; o >>= 1) {
        s  += __shfl_xor_sync(0xFFFFFFFFu, s,  o);
        s2 += __shfl_xor_sync(0xFFFFFFFFu, s2, o);
    }
    __shared__ float rs[8], rs2[8];
    int w = t >> 5, l = t & 31;
    if (l == 0) { rs[w] = s; rs2[w] = s2; }
    __syncthreads();
    if (t == 0) {
        float a = 0.f, a2 = 0.f;
        int nw = blockDim.x >> 5;
        for (int i = 0; i < nw; ++i) { a += rs[i]; a2 += rs2[i]; }
        rs[0] = a; rs2[0] = a2;
    }
    __syncthreads();
    float mean = rs[0] / (float)D;
    float var  = rs2[0] / (float)D - mean * mean;
    float inv  = rsqrtf(var + 1e-5f);
    for (int i = t; i < D; i += blockDim.x) {
        float v = (xp[i] - mean) * inv * g[i] + b[i];
        __nv_bfloat16 h = __float2bfloat16(v);
        hi[(size_t)row * D + i] = h;
        lo[(size_t)row * D + i] = __float2bfloat16(v - __bfloat162float(h));
    }
}

// ---------------- fp32 -> hi/lo bf16 (contiguous) ----------------
__global__ void split_kernel(const float* __restrict__ x,
                             __nv_bfloat16* __restrict__ hi, __nv_bfloat16* __restrict__ lo,
                             int n4)
{
    int idx = blockIdx.x * blockDim.x + threadIdx.x;
    if (idx >= n4) return;
    float4 v = *(const float4*)(x + (size_t)idx * 4);
    uint32_t* ph = (uint32_t*)(hi + (size_t)idx * 4);
    uint32_t* pl = (uint32_t*)(lo + (size_t)idx * 4);
    ph[0] = pack_hi(v.x, v.y); ph[1] = pack_hi(v.z, v.w);
    pl[0] = pack_lo(v.x, v.y); pl[1] = pack_lo(v.z, v.w);
}

// ---------------- fp32 [K,N] -> hi/lo bf16 written at [k*ldo + off + j] ------------
__global__ void split_strided(const float* __restrict__ x,
                              __nv_bfloat16* __restrict__ hi, __nv_bfloat16* __restrict__ lo,
                              int Kr, int Nc, int ldo, int off)
{
    int idx = blockIdx.x * blockDim.x + threadIdx.x;
    int n4row = Nc / 4;
    if (idx >= Kr * n4row) return;
    int k = idx / n4row, c4 = idx - k * n4row;
    float4 v = *(const float4*)(x + (size_t)k * Nc + c4 * 4);
    size_t ob = (size_t)k * ldo + off + c4 * 4;
    uint32_t* ph = (uint32_t*)(hi + ob);
    uint32_t* pl = (uint32_t*)(lo + ob);
    ph[0] = pack_hi(v.x, v.y); ph[1] = pack_hi(v.z, v.w);
    pl[0] = pack_lo(v.x, v.y); pl[1] = pack_lo(v.z, v.w);
}

// ---------------- GEGLU -> hi/lo bf16 ----------------
__global__ void geglu_split(const float* __restrict__ G,
                            __nv_bfloat16* __restrict__ hi, __nv_bfloat16* __restrict__ lo,
                            int M, int DFF)
{
    int idx = blockIdx.x * blockDim.x + threadIdx.x;
    if (idx >= M * DFF) return;
    int m = idx / DFF, j = idx - m * DFF;
    size_t base = (size_t)m * (2 * DFF);
    float a = G[base + j];
    float x = G[base + DFF + j];
    float x3 = x * x * x;
    float gl = 0.5f * x * (1.f + tanhf(0.7978845608028654f * (x + 0.044715f * x3)));
    float v = a * gl;
    __nv_bfloat16 h = __float2bfloat16(v);
    hi[idx] = h;
    lo[idx] = __float2bfloat16(v - __bfloat162float(h));
}

// ---------------- host orchestration ----------------
static inline void launch_gemm(const __nv_bfloat16* Ah, const __nv_bfloat16* Al,
                               const __nv_bfloat16* Bh, const __nv_bfloat16* Bl,
                               const float* bias, const float* resid,
                               float* C, int M, int N, int K)
{
    dim3 grid(N / 128, (M + 127) / 128);
    gemm_bf<<<grid, 256, G_SMEM>>>(Ah, Al, Bh, Bl, bias, resid, C, M, N, K);
}
static inline void launch_split(const float* x, __nv_bfloat16* h, __nv_bfloat16* l, size_t n)
{
    int n4 = (int)(n / 4);
    split_kernel<<<(n4 + 255) / 256, 256>>>(x, h, l, n4);
}
static inline void launch_split_strided(const float* x, __nv_bfloat16* h, __nv_bfloat16* l,
                                        int Kr, int Nc, int ldo, int off)
{
    int n = Kr * (Nc / 4);
    split_strided<<<(n + 255) / 256, 256>>>(x, h, l, Kr, Nc, ldo, off);
}

extern "C" void kernel_launch(void* const* d_in, const int* in_sizes, int n_in,
                              void* d_out, int out_size)
{
    const float* h1   = (const float*)d_in[0];
    const float* h2   = (const float*)d_in[1];
    const float* enc  = (const float*)d_in[2];
    const float* wq   = (const float*)d_in[3];
    const float* wk   = (const float*)d_in[4];
    const float* wv   = (const float*)d_in[5];
    const float* wqc  = (const float*)d_in[6];
    const float* wo   = (const float*)d_in[7];
    const float* bo   = (const float*)d_in[8];
    const float* ln1g = (const float*)d_in[9];
    const float* ln1b = (const float*)d_in[10];
    const float* ln2g = (const float*)d_in[11];
    const float* ln2b = (const float*)d_in[12];
    const float* w2q  = (const float*)d_in[13];
    const float* w2k  = (const float*)d_in[14];
    const float* w2v  = (const float*)d_in[15];
    const float* w2o  = (const float*)d_in[16];
    const float* b2o  = (const float*)d_in[17];
    const float* wff1 = (const float*)d_in[18];
    const float* bff1 = (const float*)d_in[19];
    const float* wff2 = (const float*)d_in[20];
    const float* bff2 = (const float*)d_in[21];

    float* H1 = (float*)d_out;
    float* H2 = H1 + NACT;

    static int attr_set = 0;
    if (!attr_set) {
        cudaFuncSetAttribute(gemm_bf,  cudaFuncAttributeMaxDynamicSharedMemorySize, G_SMEM);
        cudaFuncSetAttribute(attn_mma, cudaFuncAttributeMaxDynamicSharedMemorySize, ASMEM_BYTES);
        attr_set = 1;
    }

    float *q1, *q2, *ffp, *qkv2;
    __nv_bfloat16 *a1h, *a1l, *a2h, *a2l, *t1h, *t1l, *t2h, *t2l;
    __nv_bfloat16 *eh, *el, *fh, *fl, *wh, *wl;
    cudaGetSymbolAddress((void**)&q1,   g_q1);
    cudaGetSymbolAddress((void**)&q2,   g_q2);
    cudaGetSymbolAddress((void**)&ffp,  g_ffp);
    cudaGetSymbolAddress((void**)&qkv2, g_qkv2);
    cudaGetSymbolAddress((void**)&a1h, sA1h); cudaGetSymbolAddress((void**)&a1l, sA1l);
    cudaGetSymbolAddress((void**)&a2h, sA2h); cudaGetSymbolAddress((void**)&a2l, sA2l);
    cudaGetSymbolAddress((void**)&t1h, sT1h); cudaGetSymbolAddress((void**)&t1l, sT1l);
    cudaGetSymbolAddress((void**)&t2h, sT2h); cudaGetSymbolAddress((void**)&t2l, sT2l);
    cudaGetSymbolAddress((void**)&eh,  sEh);  cudaGetSymbolAddress((void**)&el,  sEl);
    cudaGetSymbolAddress((void**)&fh,  sFh);  cudaGetSymbolAddress((void**)&fl,  sFl);
    cudaGetSymbolAddress((void**)&wh,  sWh);  cudaGetSymbolAddress((void**)&wl,  sWl);

    const size_t DD = (size_t)Dz * Dz;
    float* qkv1 = ffp;
    float* kvE1 = ffp;                                   // MEnc x 2048 (phase B)
    float* kvE2 = ffp + (size_t)MEnc * 2048;

    // ---- Phase A: LN1 + fused QKV + dual attention ----
    ln_split<<<M1, 256>>>(h1, ln1g,      ln1b,      a1h, a1l, Dz);
    ln_split<<<M1, 256>>>(h2, ln1g + Dz, ln1b + Dz, a2h, a2l, Dz);

    launch_split_strided(wq,  wh, wl, Dz, Dz, 4096, 0);
    launch_split_strided(wk,  wh, wl, Dz, Dz, 4096, 1024);
    launch_split_strided(wv,  wh, wl, Dz, Dz, 4096, 2048);
    launch_split_strided(wqc, wh, wl, Dz, Dz, 4096, 3072);
    launch_gemm(a1h, a1l, wh, wl, nullptr, nullptr, qkv1, M1, 4096, Dz);

    __nv_bfloat16* wh2 = wh + (size_t)Dz * 4096;
    __nv_bfloat16* wl2 = wl + (size_t)Dz * 4096;
    launch_split_strided(wq  + DD, wh2, wl2, Dz, Dz, 4096, 0);
    launch_split_strided(wk  + DD, wh2, wl2, Dz, Dz, 4096, 1024);
    launch_split_strided(wv  + DD, wh2, wl2, Dz, Dz, 4096, 2048);
    launch_split_strided(wqc + DD, wh2, wl2, Dz, Dz, 4096, 3072);
    launch_gemm(a2h, a2l, wh2, wl2, nullptr, nullptr, qkv2, M1, 4096, Dz);

    dim3 agrid(Sz / 64, Bz * Hz);
    attn_mma<<<agrid, 128, ASMEM_BYTES>>>(qkv1, qkv1 + 1024, qkv1 + 2048,
                                          qkv1 + 3072, qkv2 + 1024, qkv2 + 2048,
                                          t1h, t1l, Hz, Sz, Sz, 4096, 4096, 2);
    attn_mma<<<agrid, 128, ASMEM_BYTES>>>(qkv2, qkv2 + 1024, qkv2 + 2048,
                                          qkv2 + 3072, qkv1 + 1024, qkv1 + 2048,
                                          t2h, t2l, Hz, Sz, Sz, 4096, 4096, 2);

    launch_split(wo,      wh, wl, DD);
    launch_gemm(t1h, t1l, wh, wl, bo,      h1, H1, M1, Dz, Dz);
    launch_split(wo + DD, wh, wl, DD);
    launch_gemm(t2h, t2l, wh, wl, bo + Dz, h2, H2, M1, Dz, Dz);

    // ---- Phase B: LN2 + cross attention to encoder ----
    ln_split<<<M1, 256>>>(H1, ln2g,      ln2b,      a1h, a1l, Dz);
    ln_split<<<M1, 256>>>(H2, ln2g + Dz, ln2b + Dz, a2h, a2l, Dz);

    launch_split(w2q,      wh, wl, DD);
    launch_gemm(a1h, a1l, wh, wl, nullptr, nullptr, q1, M1, Dz, Dz);
    launch_split(w2q + DD, wh, wl, DD);
    launch_gemm(a2h, a2l, wh, wl, nullptr, nullptr, q2, M1, Dz, Dz);

    launch_split(enc, eh, el, (size_t)MEnc * DEz);
    launch_split_strided(w2k, wh, wl, DEz, Dz, 2048, 0);
    launch_split_strided(w2v, wh, wl, DEz, Dz, 2048, 1024);
    launch_gemm(eh, el, wh, wl, nullptr, nullptr, kvE1, MEnc, 2048, DEz);
    launch_split_strided(w2k + (size_t)DEz * Dz, wh2, wl2, DEz, Dz, 2048, 0);
    launch_split_strided(w2v + (size_t)DEz * Dz, wh2, wl2, DEz, Dz, 2048, 1024);
    launch_gemm(eh, el, wh2, wl2, nullptr, nullptr, kvE2, MEnc, 2048, DEz);

    attn_mma<<<agrid, 128, ASMEM_BYTES>>>(q1, kvE1, kvE1 + 1024,
                                          nullptr, nullptr, nullptr,
                                          t1h, t1l, Hz, Sz, SEz, 1024, 2048, 1);
    attn_mma<<<agrid, 128, ASMEM_BYTES>>>(q2, kvE2, kvE2 + 1024,
                                          nullptr, nullptr, nullptr,
                                          t2h, t2l, Hz, Sz, SEz, 1024, 2048, 1);

    launch_split(w2o,      wh, wl, DD);
    launch_gemm(t1h, t1l, wh, wl, b2o,      H1, H1, M1, Dz, Dz);
    launch_split(w2o + DD, wh, wl, DD);
    launch_gemm(t2h, t2l, wh, wl, b2o + Dz, H2, H2, M1, Dz, Dz);

    // ---- Phase C: GEGLU feed-forward ----
    int nGeglu = M1 * DFFz;
    launch_split(wff1, wh, wl, (size_t)Dz * 2 * DFFz);
    launch_gemm(a1h, a1l, wh, wl, bff1, nullptr, ffp, M1, 2 * DFFz, Dz);
    geglu_split<<<(nGeglu + 255) / 256, 256>>>(ffp, fh, fl, M1, DFFz);
    launch_split(wff2, wh, wl, (size_t)DFFz * Dz);
    launch_gemm(fh, fl, wh, wl, bff2, H1, H1, M1, Dz, DFFz);

    launch_split(wff1 + (size_t)Dz * 2 * DFFz, wh, wl, (size_t)Dz * 2 * DFFz);
    launch_gemm(a2h, a2l, wh, wl, bff1 + 2 * DFFz, nullptr, ffp, M1, 2 * DFFz, Dz);
    geglu_split<<<(nGeglu + 255) / 256, 256>>>(ffp, fh, fl, M1, DFFz);
    launch_split(wff2 + (size_t)DFFz * Dz, wh, wl, (size_t)DFFz * Dz);
    launch_gemm(fh, fl, wh, wl, bff2 + Dz, H2, H2, M1, Dz, DFFz);
}